// round 13
// baseline (speedup 1.0000x reference)
#include <cuda_runtime.h>

// x[128,3,16,64,64] (*) w[24,3,3,3,3] VALID -> +bias -> min over depth(14) -> softmax over 24ch
// out [128,24,62,62] fp32
//
// Depth-PAIR loop: each iteration computes output depths d=2k and 2k+1 from
// slices 2k..2k+3 (6-slot ring). Slice j feeds gen A0 with kd=j and gen A1
// with kd=j-1 -> each pixel row is loaded ONCE per pair (4 loads vs 6),
// one __syncthreads per pair (7 total). 8 px x 4 oc per thread, f32x2 over
// (oc,oc+1), pixel broadcast via mov.b64 {u,u}, depth-min via smem RMW
// once per pair. (192,3).

#define THREADS 192
typedef unsigned long long ull;

__device__ __forceinline__ ull ffma2(ull a, ull b, ull c) {
    ull d;
    asm("fma.rn.f32x2 %0, %1, %2, %3;" : "=l"(d) : "l"(a), "l"(b), "l"(c));
    return d;
}
__device__ __forceinline__ ull min2(ull a, ull b) {
    float alo = __uint_as_float((unsigned)a), ahi = __uint_as_float((unsigned)(a >> 32));
    float blo = __uint_as_float((unsigned)b), bhi = __uint_as_float((unsigned)(b >> 32));
    float lo = fminf(alo, blo), hi = fminf(ahi, bhi);
    return ((ull)__float_as_uint(hi) << 32) | (ull)__float_as_uint(lo);
}
__device__ __forceinline__ ull dup(float v) {
    ull d;
    unsigned u = __float_as_uint(v);
    asm("mov.b64 %0, {%1, %1};" : "=l"(d) : "r"(u));
    return d;
}

// smem layout (floats):
//   wsm  [27 taps][6 ocg][12]        : 1944
//   ring 6 slots x [18 rows][68]     : 7344   (3cin x 6row, plain pixels, 4-col pad)
//   minbuf [256 px][26]              : 6656
#define SM_WSM   0
#define SM_RING  1944
#define SM_MIN   9288
#define SM_TOTAL 15944   // floats = 63776 bytes

__device__ __forceinline__ void loadpp(const float* __restrict__ pr,
                                       ull (&ppA)[6], ull (&ppB)[6])
{
    float4 q  = *(const float4*)pr;
    float2 q2 = *(const float2*)(pr + 4);
    ppA[0] = dup(q.x); ppA[1] = dup(q.y); ppA[2] = dup(q.z);
    ppA[3] = dup(q.w); ppA[4] = dup(q2.x); ppA[5] = dup(q2.y);
    float4 s  = *(const float4*)(pr + 32);
    float2 s2 = *(const float2*)(pr + 36);
    ppB[0] = dup(s.x); ppB[1] = dup(s.y); ppB[2] = dup(s.z);
    ppB[3] = dup(s.w); ppB[4] = dup(s2.x); ppB[5] = dup(s2.y);
}

// apply one kd tap-set (12 weight floats) to one generation's 16 accs
__device__ __forceinline__ void applyt(const float* __restrict__ wb, ull (&A)[16],
                                       const ull (&ppA)[6], const ull (&ppB)[6])
{
    ulonglong2 v0 = *(const ulonglong2*)(wb);        // kw0: jp0, jp1
    ulonglong2 v1 = *(const ulonglong2*)(wb + 4);    // kw1
    ulonglong2 v2 = *(const ulonglong2*)(wb + 8);    // kw2
    ull w[3][2] = { { v0.x, v0.y }, { v1.x, v1.y }, { v2.x, v2.y } };
    #pragma unroll
    for (int kw = 0; kw < 3; ++kw)
        #pragma unroll
        for (int jp = 0; jp < 2; ++jp) {
            #pragma unroll
            for (int px = 0; px < 4; ++px)
                A[jp * 8 + px]     = ffma2(w[kw][jp], ppA[px + kw], A[jp * 8 + px]);
            #pragma unroll
            for (int px = 0; px < 4; ++px)
                A[jp * 8 + 4 + px] = ffma2(w[kw][jp], ppB[px + kw], A[jp * 8 + 4 + px]);
        }
}

// depth-min RMW in smem, once per pair per generation
template<bool FIRST>
__device__ __forceinline__ void fold(float* __restrict__ minbuf, int r, int w0, int oc0,
                                     ull (&A)[16], const ull (&bini)[2])
{
    #pragma unroll
    for (int jp = 0; jp < 2; ++jp)
        #pragma unroll
        for (int hf = 0; hf < 2; ++hf)
            #pragma unroll
            for (int px = 0; px < 4; ++px) {
                int pix = r * 64 + hf * 32 + w0 + px;
                ull* q = (ull*)(minbuf + pix * 26 + oc0 + 2 * jp);
                ull a = A[jp * 8 + hf * 4 + px];
                if (FIRST) *q = a;
                else       *q = min2(*q, a);
                A[jp * 8 + hf * 4 + px] = bini[jp];
            }
}

__device__ __forceinline__ void stage_ldg(const float* __restrict__ xb, int r0, int tid,
                                          int s, float (&stg)[6]) {
    #pragma unroll
    for (int k = 0; k < 6; ++k) {
        int i = tid + k * THREADS;                 // 0..1151 = 3cin*6row*64w
        int cin = i / 384, rem = i % 384;
        int row = rem >> 6, w = rem & 63;
        int gr = min(r0 + row, 63);
        stg[k] = xb[((cin * 16 + s) << 12) + (gr << 6) + w];
    }
}
__device__ __forceinline__ void stage_sts(float* __restrict__ ring, int slot, int tid,
                                          const float (&stg)[6]) {
    float* sl = ring + slot * 1224;
    #pragma unroll
    for (int k = 0; k < 6; ++k) {
        int i = tid + k * THREADS;
        int cin = i / 384, rem = i % 384;
        int row = rem >> 6, w = rem & 63;
        sl[(cin * 6 + row) * 68 + w] = stg[k];
    }
}

__global__ __launch_bounds__(THREADS, 3)
void conv3d_min_softmax_kernel(const float* __restrict__ x,
                               const float* __restrict__ wgt,
                               const float* __restrict__ bias,
                               float* __restrict__ out)
{
    extern __shared__ float smem[];
    float* wsm    = smem + SM_WSM;
    float* ring   = smem + SM_RING;
    float* minbuf = smem + SM_MIN;

    const int tid = threadIdx.x;
    const int b   = blockIdx.y;
    const int r0  = blockIdx.x * 4;     // 0..60

    // ---- stage weights: [tap][ocg][ (kw*2+jp)*2+lane ] ----
    for (int i = tid; i < 1944; i += THREADS) {
        int tap = i / 72, rem = i % 72;
        int ocg_ = rem / 12, f = rem % 12;
        int p = f >> 1, lane = f & 1;
        int kw = p >> 1, jp = p & 1;
        int oc = ocg_ * 4 + jp * 2 + lane;
        wsm[i] = wgt[oc * 81 + tap * 3 + kw];
    }
    // zero image pads (cols 64..67 of each row, all 6 slots)
    for (int i = tid; i < 432; i += THREADS) {
        int slot = i / 72, rem = i % 72;
        int row = rem >> 2, c = rem & 3;
        ring[slot * 1224 + row * 68 + 64 + c] = 0.f;
    }

    const float* xb = x + (size_t)b * (3 * 16 * 4096);
    float stgA[6], stgB[6];

    // prologue: slices 0,1 -> slots 0,1; prefetch slices 2,3
    stage_ldg(xb, r0, tid, 0, stgA); stage_sts(ring, 0, tid, stgA);
    stage_ldg(xb, r0, tid, 1, stgA); stage_sts(ring, 1, tid, stgA);
    stage_ldg(xb, r0, tid, 2, stgA);
    stage_ldg(xb, r0, tid, 3, stgB);

    const int ocg = tid >> 5;            // 0..5, warp-uniform -> weight broadcast
    const int g   = tid & 31;
    const int r   = g >> 3;              // tile row 0..3
    const int w0  = (g & 7) * 4;         // quad A at w0, quad B at w0+32
    const int oc0 = ocg * 4;

    ull bini[2];
    #pragma unroll
    for (int jp = 0; jp < 2; ++jp)
        bini[jp] = *(const ull*)(bias + oc0 + 2 * jp);

    ull A0[16], A1[16];
    #pragma unroll
    for (int t = 0; t < 16; ++t) { A0[t] = bini[t >> 3]; A1[t] = bini[t >> 3]; }

    int slo = 0;   // slot index of slice 2k

    #pragma unroll 1
    for (int k = 0; k < 7; ++k) {        // pair iter: d = 2k, 2k+1
        // store prefetched slices 2k+2, 2k+3 (slots last read in iter k-2)
        stage_sts(ring, (slo + 2) % 6, tid, stgA);
        stage_sts(ring, (slo + 3) % 6, tid, stgB);
        if (k < 6) {
            stage_ldg(xb, r0, tid, 2 * k + 4, stgA);
            stage_ldg(xb, r0, tid, 2 * k + 5, stgB);
        }
        __syncthreads();                 // sts (2k+2,2k+3) before reads; also ends iter k-1 reads

        const float* s0 = ring + ((slo    ) % 6) * 1224;
        const float* s1 = ring + ((slo + 1) % 6) * 1224;
        const float* s2 = ring + ((slo + 2) % 6) * 1224;
        const float* s3 = ring + ((slo + 3) % 6) * 1224;

        #pragma unroll 1
        for (int ck = 0; ck < 9; ++ck) {           // ck = cin*3 + kh
            int cin = ck / 3, kh = ck % 3;
            int rowoff = (cin * 6 + r + kh) * 68 + w0;
            const float* wt = wsm + ((cin * 9 + kh) * 6 + ocg) * 12;   // kd=0 tap

            ull ppA[6], ppB[6];
            loadpp(s0 + rowoff, ppA, ppB);         // slice 2k
            applyt(wt,       A0, ppA, ppB);        //   kd0 -> d=2k

            loadpp(s1 + rowoff, ppA, ppB);         // slice 2k+1
            applyt(wt + 216, A0, ppA, ppB);        //   kd1 -> d=2k
            applyt(wt,       A1, ppA, ppB);        //   kd0 -> d=2k+1

            loadpp(s2 + rowoff, ppA, ppB);         // slice 2k+2
            applyt(wt + 432, A0, ppA, ppB);        //   kd2 -> d=2k
            applyt(wt + 216, A1, ppA, ppB);        //   kd1 -> d=2k+1

            loadpp(s3 + rowoff, ppA, ppB);         // slice 2k+3
            applyt(wt + 432, A1, ppA, ppB);        //   kd2 -> d=2k+1
        }

        if (k == 0) fold<true >(minbuf, r, w0, oc0, A0, bini);
        else        fold<false>(minbuf, r, w0, oc0, A0, bini);
        fold<false>(minbuf, r, w0, oc0, A1, bini);  // d=2k+1 mins against d=2k

        slo = (slo + 2) % 6;
    }

    __syncthreads();

    // ---- softmax over 24 channels per pixel (256 pixels) ----
    for (int p = tid; p < 256; p += THREADS) {
        float* row = minbuf + p * 26;
        float m = -3.402823466e38f;
        #pragma unroll
        for (int oc = 0; oc < 24; ++oc) m = fmaxf(m, row[oc]);
        float ssum = 0.f;
        #pragma unroll
        for (int oc = 0; oc < 24; ++oc) {
            float e = __expf(row[oc] - m);
            row[oc] = e;
            ssum += e;
        }
        float rinv = 1.0f / ssum;
        #pragma unroll
        for (int oc = 0; oc < 24; ++oc) row[oc] *= rinv;
    }
    __syncthreads();

    // ---- coalesced store ----
    float* ob = out + (size_t)b * (24 * 62 * 62);
    for (int i = tid; i < 24 * 256; i += THREADS) {
        int oc = i >> 8, pix = i & 255;
        int row = pix >> 6, w = pix & 63;
        int oh = r0 + row;
        if (w < 62 && oh < 62)
            ob[(oc * 62 + oh) * 62 + w] = minbuf[pix * 26 + oc];
    }
}

extern "C" void kernel_launch(void* const* d_in, const int* in_sizes, int n_in,
                              void* d_out, int out_size) {
    const float* x    = (const float*)d_in[0];
    const float* wgt  = (const float*)d_in[1];
    const float* bias = (const float*)d_in[2];
    float* out = (float*)d_out;

    cudaFuncSetAttribute(conv3d_min_softmax_kernel,
                         cudaFuncAttributeMaxDynamicSharedMemorySize,
                         SM_TOTAL * (int)sizeof(float));
    dim3 grid(16, 128);   // 16 four-row tiles x 128 batches
    conv3d_min_softmax_kernel<<<grid, THREADS, SM_TOTAL * sizeof(float)>>>(x, wgt, bias, out);
}

// round 14
// speedup vs baseline: 1.2565x; 1.2565x over previous
#include <cuda_runtime.h>

// x[128,3,16,64,64] (*) w[24,3,3,3,3] VALID -> +bias -> min over depth(14) -> softmax over 24ch
// out [128,24,62,62] fp32
//
// Depth-major single-generation loop (R12 structure), but 4 fat warps:
// each thread computes 6 oc x 8 px (3 oc-pairs, two conflict-free quads).
// Fewer warps sharing the tile -> pixel LDS redundancy 6x -> 4x.
// f32x2 over (oc,oc+1), pixel broadcast via mov.b64 {u,u}, min in registers,
// one __syncthreads per depth. 4-row tiles, (128,3).

#define THREADS 128
typedef unsigned long long ull;

__device__ __forceinline__ ull ffma2(ull a, ull b, ull c) {
    ull d;
    asm("fma.rn.f32x2 %0, %1, %2, %3;" : "=l"(d) : "l"(a), "l"(b), "l"(c));
    return d;
}
__device__ __forceinline__ ull min2(ull a, ull b) {
    float alo = __uint_as_float((unsigned)a), ahi = __uint_as_float((unsigned)(a >> 32));
    float blo = __uint_as_float((unsigned)b), bhi = __uint_as_float((unsigned)(b >> 32));
    float lo = fminf(alo, blo), hi = fminf(ahi, bhi);
    return ((ull)__float_as_uint(hi) << 32) | (ull)__float_as_uint(lo);
}
__device__ __forceinline__ ull dup(float v) {
    ull d;
    unsigned u = __float_as_uint(v);
    asm("mov.b64 %0, {%1, %1};" : "=l"(d) : "r"(u));
    return d;
}

// smem layout (floats):
//   wsm  [27 taps][4 ocg][20]        : 2160   (9 pairs = 3kw x 3jp, 2-float pad)
//   ring 4 slots x [18 rows][68]     : 4896   (3cin x 6row, plain pixels, 4-col pad)
//   minbuf [256 px][26]              : 6656
#define SM_WSM   0
#define SM_RING  2160
#define SM_MIN   7056
#define SM_TOTAL 13712   // floats = 54848 bytes

// one (cin,kh,kd) tap-row: 18 weight floats (9 pairs) x 12 pixels -> 72 FFMA2
__device__ __forceinline__ void body(const float* __restrict__ pr,
                                     const float* __restrict__ wb,
                                     ull (&A)[24])
{
    // pixels: two quads (w0.., w0+32..), 6 cols each
    float4 q  = *(const float4*)pr;
    float2 q2 = *(const float2*)(pr + 4);
    ull ppA[6] = { dup(q.x), dup(q.y), dup(q.z), dup(q.w), dup(q2.x), dup(q2.y) };
    float4 s  = *(const float4*)(pr + 32);
    float2 s2 = *(const float2*)(pr + 36);
    ull ppB[6] = { dup(s.x), dup(s.y), dup(s.z), dup(s.w), dup(s2.x), dup(s2.y) };

    // weights: 9 pairs, broadcast loads
    ulonglong2 v0 = *(const ulonglong2*)(wb);        // (kw0,jp0) (kw0,jp1)
    ulonglong2 v1 = *(const ulonglong2*)(wb + 4);    // (kw0,jp2) (kw1,jp0)
    ulonglong2 v2 = *(const ulonglong2*)(wb + 8);    // (kw1,jp1) (kw1,jp2)
    ulonglong2 v3 = *(const ulonglong2*)(wb + 12);   // (kw2,jp0) (kw2,jp1)
    ull        v4 = *(const ull*)(wb + 16);          // (kw2,jp2)
    ull w[3][3] = { { v0.x, v0.y, v1.x },
                    { v1.y, v2.x, v2.y },
                    { v3.x, v3.y, v4 } };

    #pragma unroll
    for (int kw = 0; kw < 3; ++kw)
        #pragma unroll
        for (int jp = 0; jp < 3; ++jp) {
            #pragma unroll
            for (int px = 0; px < 4; ++px)
                A[jp * 8 + px]     = ffma2(w[kw][jp], ppA[px + kw], A[jp * 8 + px]);
            #pragma unroll
            for (int px = 0; px < 4; ++px)
                A[jp * 8 + 4 + px] = ffma2(w[kw][jp], ppB[px + kw], A[jp * 8 + 4 + px]);
        }
}

__device__ __forceinline__ void stage_ldg(const float* __restrict__ xb, int r0, int tid,
                                          int s, float (&stg)[9]) {
    #pragma unroll
    for (int k = 0; k < 9; ++k) {
        int i = tid + k * THREADS;                 // 0..1151 = 3cin*6row*64w
        int cin = i / 384, rem = i % 384;
        int row = rem >> 6, w = rem & 63;
        int gr = min(r0 + row, 63);
        stg[k] = xb[((cin * 16 + s) << 12) + (gr << 6) + w];
    }
}
__device__ __forceinline__ void stage_sts(float* __restrict__ ring, int slot, int tid,
                                          const float (&stg)[9]) {
    float* sl = ring + slot * 1224;
    #pragma unroll
    for (int k = 0; k < 9; ++k) {
        int i = tid + k * THREADS;
        int cin = i / 384, rem = i % 384;
        int row = rem >> 6, w = rem & 63;
        sl[(cin * 6 + row) * 68 + w] = stg[k];
    }
}

__global__ __launch_bounds__(THREADS, 3)
void conv3d_min_softmax_kernel(const float* __restrict__ x,
                               const float* __restrict__ wgt,
                               const float* __restrict__ bias,
                               float* __restrict__ out)
{
    extern __shared__ float smem[];
    float* wsm    = smem + SM_WSM;
    float* ring   = smem + SM_RING;
    float* minbuf = smem + SM_MIN;

    const int tid = threadIdx.x;
    const int b   = blockIdx.y;
    const int r0  = blockIdx.x * 4;     // 0..60

    // ---- stage weights: [tap][ocg][ (kw*3+jp)*2+lane ], stride 20 ----
    for (int i = tid; i < 1944; i += THREADS) {
        int tap = i / 72, rem = i % 72;
        int ocg_ = rem / 18, f = rem % 18;
        int p = f >> 1, lane = f & 1;
        int kw = p / 3, jp = p % 3;
        int oc = ocg_ * 6 + jp * 2 + lane;
        wsm[(tap * 4 + ocg_) * 20 + p * 2 + lane] = wgt[oc * 81 + tap * 3 + kw];
    }
    // zero image pads (cols 64..67 of each row, all 4 slots)
    for (int i = tid; i < 288; i += THREADS) {
        int slot = i / 72, rem = i % 72;
        int row = rem >> 2, c = rem & 3;
        ring[slot * 1224 + row * 68 + 64 + c] = 0.f;
    }

    const float* xb = x + (size_t)b * (3 * 16 * 4096);
    float stg[9];

    // prologue: slices 0,1 to slots 0,1; prefetch slice 2
    stage_ldg(xb, r0, tid, 0, stg); stage_sts(ring, 0, tid, stg);
    stage_ldg(xb, r0, tid, 1, stg); stage_sts(ring, 1, tid, stg);
    stage_ldg(xb, r0, tid, 2, stg);

    const int ocg = tid >> 5;            // 0..3, warp-uniform -> weight broadcast
    const int g   = tid & 31;
    const int r   = g >> 3;              // tile row 0..3
    const int w0  = (g & 7) * 4;         // quad A at w0, quad B at w0+32
    const int oc0 = ocg * 6;

    ull bini[3];
    #pragma unroll
    for (int jp = 0; jp < 3; ++jp)
        bini[jp] = *(const ull*)(bias + oc0 + 2 * jp);

    ull A[24];
    #pragma unroll
    for (int t = 0; t < 24; ++t) A[t] = bini[t >> 3];

    const ull INF2 = 0x7F8000007F800000ULL;
    ull mn[24];
    #pragma unroll
    for (int t = 0; t < 24; ++t) mn[t] = INF2;

    #pragma unroll 1
    for (int d = 0; d < 14; ++d) {
        // slot (d+2)&3 held slice d-2 (last read at compute(d-2); the sync
        // inside iteration d-1 ordered those reads before this store)
        stage_sts(ring, (d + 2) & 3, tid, stg);
        if (d + 3 <= 15) stage_ldg(xb, r0, tid, d + 3, stg);
        __syncthreads();

        const float* s0 = ring + ((d    ) & 3) * 1224;
        const float* s1 = ring + ((d + 1) & 3) * 1224;
        const float* s2 = ring + ((d + 2) & 3) * 1224;

        #pragma unroll 1
        for (int ck = 0; ck < 9; ++ck) {           // ck = cin*3 + kh
            int cin = ck / 3, kh = ck % 3;
            int rowoff = (cin * 6 + r + kh) * 68 + w0;
            const float* wt = wsm + ((cin * 9 + kh) * 4 + ocg) * 20;   // kd=0 tap
            body(s0 + rowoff, wt,       A);        // kd=0
            body(s1 + rowoff, wt + 240, A);        // kd=1 (+3 taps * 80)
            body(s2 + rowoff, wt + 480, A);        // kd=2
        }

        #pragma unroll
        for (int t = 0; t < 24; ++t) {
            mn[t] = min2(mn[t], A[t]);
            A[t] = bini[t >> 3];
        }
    }

    // ---- write per-thread mins to smem ----
    #pragma unroll
    for (int jp = 0; jp < 3; ++jp)
        #pragma unroll
        for (int hf = 0; hf < 2; ++hf)
            #pragma unroll
            for (int px = 0; px < 4; ++px) {
                int pix = r * 64 + hf * 32 + w0 + px;
                *(ull*)(minbuf + pix * 26 + oc0 + 2 * jp) = mn[jp * 8 + hf * 4 + px];
            }
    __syncthreads();

    // ---- softmax over 24 channels per pixel (256 pixels) ----
    for (int p = tid; p < 256; p += THREADS) {
        float* row = minbuf + p * 26;
        float m = -3.402823466e38f;
        #pragma unroll
        for (int oc = 0; oc < 24; ++oc) m = fmaxf(m, row[oc]);
        float ssum = 0.f;
        #pragma unroll
        for (int oc = 0; oc < 24; ++oc) {
            float e = __expf(row[oc] - m);
            row[oc] = e;
            ssum += e;
        }
        float rinv = 1.0f / ssum;
        #pragma unroll
        for (int oc = 0; oc < 24; ++oc) row[oc] *= rinv;
    }
    __syncthreads();

    // ---- coalesced store ----
    float* ob = out + (size_t)b * (24 * 62 * 62);
    for (int i = tid; i < 24 * 256; i += THREADS) {
        int oc = i / 256, pix = i & 255;
        int row = pix >> 6, w = pix & 63;
        int oh = r0 + row;
        if (w < 62 && oh < 62)
            ob[(oc * 62 + oh) * 62 + w] = minbuf[pix * 26 + oc];
    }
}

extern "C" void kernel_launch(void* const* d_in, const int* in_sizes, int n_in,
                              void* d_out, int out_size) {
    const float* x    = (const float*)d_in[0];
    const float* wgt  = (const float*)d_in[1];
    const float* bias = (const float*)d_in[2];
    float* out = (float*)d_out;

    cudaFuncSetAttribute(conv3d_min_softmax_kernel,
                         cudaFuncAttributeMaxDynamicSharedMemorySize,
                         SM_TOTAL * (int)sizeof(float));
    dim3 grid(16, 128);   // 16 four-row tiles x 128 batches
    conv3d_min_softmax_kernel<<<grid, THREADS, SM_TOTAL * sizeof(float)>>>(x, wgt, bias, out);
}

// round 15
// speedup vs baseline: 1.3589x; 1.0815x over previous
#include <cuda_runtime.h>

// x[128,3,16,64,64] (*) w[24,3,3,3,3] VALID -> +bias -> min over depth(14) -> softmax over 24ch
// out [128,24,62,62] fp32
//
// Depth-major single-generation loop, 4 fat warps: each thread 6 oc x 8 px
// (3 oc-pairs, two conflict-free quads). f32x2 over (oc,oc+1), pixel
// broadcast via mov.b64 {u,u}, min in registers, one __syncthreads per
// depth. This round: float4-vectorized slice staging (9 scalar -> ~2.25
// vector LDG/STS per thread) and ck-loop unroll 3 for cross-body LDS/FFMA
// overlap. 4-row tiles, (128,3).

#define THREADS 128
typedef unsigned long long ull;

__device__ __forceinline__ ull ffma2(ull a, ull b, ull c) {
    ull d;
    asm("fma.rn.f32x2 %0, %1, %2, %3;" : "=l"(d) : "l"(a), "l"(b), "l"(c));
    return d;
}
__device__ __forceinline__ ull min2(ull a, ull b) {
    float alo = __uint_as_float((unsigned)a), ahi = __uint_as_float((unsigned)(a >> 32));
    float blo = __uint_as_float((unsigned)b), bhi = __uint_as_float((unsigned)(b >> 32));
    float lo = fminf(alo, blo), hi = fminf(ahi, bhi);
    return ((ull)__float_as_uint(hi) << 32) | (ull)__float_as_uint(lo);
}
__device__ __forceinline__ ull dup(float v) {
    ull d;
    unsigned u = __float_as_uint(v);
    asm("mov.b64 %0, {%1, %1};" : "=l"(d) : "r"(u));
    return d;
}

// smem layout (floats):
//   wsm  [27 taps][4 ocg][20]        : 2160   (9 pairs = 3kw x 3jp, 2-float pad)
//   ring 4 slots x [18 rows][68]     : 4896   (3cin x 6row, plain pixels, 4-col pad)
//   minbuf [256 px][26]              : 6656
#define SM_WSM   0
#define SM_RING  2160
#define SM_MIN   7056
#define SM_TOTAL 13712   // floats = 54848 bytes

// one (cin,kh,kd) tap-row: 18 weight floats (9 pairs) x 12 pixels -> 72 FFMA2
__device__ __forceinline__ void body(const float* __restrict__ pr,
                                     const float* __restrict__ wb,
                                     ull (&A)[24])
{
    // pixels: two quads (w0.., w0+32..), 6 cols each
    float4 q  = *(const float4*)pr;
    float2 q2 = *(const float2*)(pr + 4);
    ull ppA[6] = { dup(q.x), dup(q.y), dup(q.z), dup(q.w), dup(q2.x), dup(q2.y) };
    float4 s  = *(const float4*)(pr + 32);
    float2 s2 = *(const float2*)(pr + 36);
    ull ppB[6] = { dup(s.x), dup(s.y), dup(s.z), dup(s.w), dup(s2.x), dup(s2.y) };

    // weights: 9 pairs, broadcast loads
    ulonglong2 v0 = *(const ulonglong2*)(wb);        // (kw0,jp0) (kw0,jp1)
    ulonglong2 v1 = *(const ulonglong2*)(wb + 4);    // (kw0,jp2) (kw1,jp0)
    ulonglong2 v2 = *(const ulonglong2*)(wb + 8);    // (kw1,jp1) (kw1,jp2)
    ulonglong2 v3 = *(const ulonglong2*)(wb + 12);   // (kw2,jp0) (kw2,jp1)
    ull        v4 = *(const ull*)(wb + 16);          // (kw2,jp2)
    ull w[3][3] = { { v0.x, v0.y, v1.x },
                    { v1.y, v2.x, v2.y },
                    { v3.x, v3.y, v4 } };

    #pragma unroll
    for (int kw = 0; kw < 3; ++kw)
        #pragma unroll
        for (int jp = 0; jp < 3; ++jp) {
            #pragma unroll
            for (int px = 0; px < 4; ++px)
                A[jp * 8 + px]     = ffma2(w[kw][jp], ppA[px + kw], A[jp * 8 + px]);
            #pragma unroll
            for (int px = 0; px < 4; ++px)
                A[jp * 8 + 4 + px] = ffma2(w[kw][jp], ppB[px + kw], A[jp * 8 + 4 + px]);
        }
}

// slice staging as float4: 1152 floats = 288 float4 per slice
__device__ __forceinline__ void stage_ldg(const float* __restrict__ xb, int r0, int tid,
                                          int s, float4 (&stg)[3]) {
    #pragma unroll
    for (int k = 0; k < 3; ++k) {
        int f = tid + k * THREADS;                 // 0..287 valid
        if (k < 2 || tid < 32) {
            int cin = f / 96, rem = f % 96;
            int row = rem >> 4, w4 = rem & 15;
            int gr = min(r0 + row, 63);
            stg[k] = *(const float4*)(xb + ((cin * 16 + s) << 12) + (gr << 6) + w4 * 4);
        }
    }
}
__device__ __forceinline__ void stage_sts(float* __restrict__ ring, int slot, int tid,
                                          const float4 (&stg)[3]) {
    float* sl = ring + slot * 1224;
    #pragma unroll
    for (int k = 0; k < 3; ++k) {
        int f = tid + k * THREADS;
        if (k < 2 || tid < 32) {
            int cin = f / 96, rem = f % 96;
            int row = rem >> 4, w4 = rem & 15;
            *(float4*)(sl + (cin * 6 + row) * 68 + w4 * 4) = stg[k];
        }
    }
}

__global__ __launch_bounds__(THREADS, 3)
void conv3d_min_softmax_kernel(const float* __restrict__ x,
                               const float* __restrict__ wgt,
                               const float* __restrict__ bias,
                               float* __restrict__ out)
{
    extern __shared__ float smem[];
    float* wsm    = smem + SM_WSM;
    float* ring   = smem + SM_RING;
    float* minbuf = smem + SM_MIN;

    const int tid = threadIdx.x;
    const int b   = blockIdx.y;
    const int r0  = blockIdx.x * 4;     // 0..60

    // ---- stage weights: [tap][ocg][ (kw*3+jp)*2+lane ], stride 20 ----
    for (int i = tid; i < 1944; i += THREADS) {
        int tap = i / 72, rem = i % 72;
        int ocg_ = rem / 18, f = rem % 18;
        int p = f >> 1, lane = f & 1;
        int kw = p / 3, jp = p % 3;
        int oc = ocg_ * 6 + jp * 2 + lane;
        wsm[(tap * 4 + ocg_) * 20 + p * 2 + lane] = wgt[oc * 81 + tap * 3 + kw];
    }
    // zero image pads (cols 64..67 of each row, all 4 slots)
    for (int i = tid; i < 288; i += THREADS) {
        int slot = i / 72, rem = i % 72;
        int row = rem >> 2, c = rem & 3;
        ring[slot * 1224 + row * 68 + 64 + c] = 0.f;
    }

    const float* xb = x + (size_t)b * (3 * 16 * 4096);
    float4 stg[3];

    // prologue: slices 0,1 to slots 0,1; prefetch slice 2
    stage_ldg(xb, r0, tid, 0, stg); stage_sts(ring, 0, tid, stg);
    stage_ldg(xb, r0, tid, 1, stg); stage_sts(ring, 1, tid, stg);
    stage_ldg(xb, r0, tid, 2, stg);

    const int ocg = tid >> 5;            // 0..3, warp-uniform -> weight broadcast
    const int g   = tid & 31;
    const int r   = g >> 3;              // tile row 0..3
    const int w0  = (g & 7) * 4;         // quad A at w0, quad B at w0+32
    const int oc0 = ocg * 6;

    ull bini[3];
    #pragma unroll
    for (int jp = 0; jp < 3; ++jp)
        bini[jp] = *(const ull*)(bias + oc0 + 2 * jp);

    ull A[24];
    #pragma unroll
    for (int t = 0; t < 24; ++t) A[t] = bini[t >> 3];

    const ull INF2 = 0x7F8000007F800000ULL;
    ull mn[24];
    #pragma unroll
    for (int t = 0; t < 24; ++t) mn[t] = INF2;

    #pragma unroll 1
    for (int d = 0; d < 14; ++d) {
        // slot (d+2)&3 held slice d-2 (last read at compute(d-2); the sync
        // inside iteration d-1 ordered those reads before this store)
        stage_sts(ring, (d + 2) & 3, tid, stg);
        if (d + 3 <= 15) stage_ldg(xb, r0, tid, d + 3, stg);
        __syncthreads();

        const float* s0 = ring + ((d    ) & 3) * 1224;
        const float* s1 = ring + ((d + 1) & 3) * 1224;
        const float* s2 = ring + ((d + 2) & 3) * 1224;

        #pragma unroll 3
        for (int ck = 0; ck < 9; ++ck) {           // ck = cin*3 + kh
            int cin = ck / 3, kh = ck % 3;
            int rowoff = (cin * 6 + r + kh) * 68 + w0;
            const float* wt = wsm + ((cin * 9 + kh) * 4 + ocg) * 20;   // kd=0 tap
            body(s0 + rowoff, wt,       A);        // kd=0
            body(s1 + rowoff, wt + 240, A);        // kd=1 (+3 taps * 80)
            body(s2 + rowoff, wt + 480, A);        // kd=2
        }

        #pragma unroll
        for (int t = 0; t < 24; ++t) {
            mn[t] = min2(mn[t], A[t]);
            A[t] = bini[t >> 3];
        }
    }

    // ---- write per-thread mins to smem ----
    #pragma unroll
    for (int jp = 0; jp < 3; ++jp)
        #pragma unroll
        for (int hf = 0; hf < 2; ++hf)
            #pragma unroll
            for (int px = 0; px < 4; ++px) {
                int pix = r * 64 + hf * 32 + w0 + px;
                *(ull*)(minbuf + pix * 26 + oc0 + 2 * jp) = mn[jp * 8 + hf * 4 + px];
            }
    __syncthreads();

    // ---- softmax over 24 channels per pixel (256 pixels) ----
    for (int p = tid; p < 256; p += THREADS) {
        float* row = minbuf + p * 26;
        float m = -3.402823466e38f;
        #pragma unroll
        for (int oc = 0; oc < 24; ++oc) m = fmaxf(m, row[oc]);
        float ssum = 0.f;
        #pragma unroll
        for (int oc = 0; oc < 24; ++oc) {
            float e = __expf(row[oc] - m);
            row[oc] = e;
            ssum += e;
        }
        float rinv = 1.0f / ssum;
        #pragma unroll
        for (int oc = 0; oc < 24; ++oc) row[oc] *= rinv;
    }
    __syncthreads();

    // ---- coalesced store ----
    float* ob = out + (size_t)b * (24 * 62 * 62);
    for (int i = tid; i < 24 * 256; i += THREADS) {
        int oc = i / 256, pix = i & 255;
        int row = pix >> 6, w = pix & 63;
        int oh = r0 + row;
        if (w < 62 && oh < 62)
            ob[(oc * 62 + oh) * 62 + w] = minbuf[pix * 26 + oc];
    }
}

extern "C" void kernel_launch(void* const* d_in, const int* in_sizes, int n_in,
                              void* d_out, int out_size) {
    const float* x    = (const float*)d_in[0];
    const float* wgt  = (const float*)d_in[1];
    const float* bias = (const float*)d_in[2];
    float* out = (float*)d_out;

    cudaFuncSetAttribute(conv3d_min_softmax_kernel,
                         cudaFuncAttributeMaxDynamicSharedMemorySize,
                         SM_TOTAL * (int)sizeof(float));
    dim3 grid(16, 128);   // 16 four-row tiles x 128 batches
    conv3d_min_softmax_kernel<<<grid, THREADS, SM_TOTAL * sizeof(float)>>>(x, wgt, bias, out);
}